// round 6
// baseline (speedup 1.0000x reference)
#include <cuda_runtime.h>
#include <cuda_bf16.h>
#include <stdint.h>
#include <math.h>

// Volume: D=64, H=128, W=128 ; B=2, C=4  (fixed shapes)
#define DZ 64
#define HY 128
#define WX 128
#define HW (HY * WX)          // 16384
#define NVOX (DZ * HY * WX)   // 1,048,576
#define NMASK 12
#define NPROB 36
#define TZ 8
#define TY 8
#define TILE_VOX (TZ * TY * WX)   // 8192

typedef unsigned int u32;
typedef unsigned char u8;

// Scratch (device globals)
__device__ u8  g_mask[NMASK * NVOX];       // 12 MB
__device__ u8  g_reach[NMASK * NVOX];      // 12 MB
__device__ int g_L[(size_t)NPROB * NVOX];  // 144 MB
__device__ int g_cnt[NPROB];

// ---------------- union-find (works on global or shared via generic ptr) ----
__device__ __forceinline__ int uf_find(int* L, int x) {
    while (true) {
        int p = L[x];
        if (p == x) return x;
        int gp = L[p];
        if (gp != p) L[x] = gp;   // path halving
        x = gp;
    }
}

__device__ __forceinline__ void uf_union(int* L, int a, int b) {
    while (true) {
        a = uf_find(L, a);
        b = uf_find(L, b);
        if (a == b) return;
        if (a > b) { int t = a; a = b; b = t; }
        int old = atomicMin(&L[b], a);
        if (old == b) return;
        b = old;
    }
}

// count of consecutive set bits strictly below position x in a 128-bit row bitmap
__device__ __forceinline__ int trailing_run(const u32* bits, int x) {
    int r = 0;
    int w = x >> 5, b = x & 31;
    if (b) {
        u32 below = bits[w] << (32 - b);   // top b bits = bits below x
        int ones = __clz(~below);
        if (ones < b) return ones;
        r = b;
    }
    for (int ww = w - 1; ww >= 0; --ww) {
        u32 word = bits[ww];
        if (word == 0xffffffffu) { r += 32; continue; }
        return r + __clz(~word);
    }
    return r;
}

// ---------------- kernels ----------------

__global__ void k_zero_counters() {
    int i = threadIdx.x;
    if (i < NPROB) g_cnt[i] = 0;
}

// Build 6 pred masks + 6 target masks, 4 voxels/thread.  grid:(NVOX/1024, 2)
__global__ void k_masks(const float* __restrict__ pred, const int* __restrict__ target) {
    int b = blockIdx.y;
    int vbase = (blockIdx.x * 256 + threadIdx.x) * 4;
    const float* pp = pred + (size_t)b * 4 * NVOX + vbase;
    float4 a0 = *(const float4*)(pp);
    float4 a1 = *(const float4*)(pp + NVOX);
    float4 a2 = *(const float4*)(pp + 2 * NVOX);
    float4 a3 = *(const float4*)(pp + 3 * NVOX);
    int4 t = *(const int4*)(target + (size_t)b * NVOX + vbase);

    u8 m1[4], m2[4], m3[4];
    float x0s[4] = {a0.x, a0.y, a0.z, a0.w};
    float x1s[4] = {a1.x, a1.y, a1.z, a1.w};
    float x2s[4] = {a2.x, a2.y, a2.z, a2.w};
    float x3s[4] = {a3.x, a3.y, a3.z, a3.w};
    #pragma unroll
    for (int i = 0; i < 4; i++) {
        float m = fmaxf(fmaxf(x0s[i], x1s[i]), fmaxf(x2s[i], x3s[i]));
        float e0 = expf(x0s[i] - m), e1 = expf(x1s[i] - m);
        float e2 = expf(x2s[i] - m), e3 = expf(x3s[i] - m);
        float h = 0.5f * (e0 + e1 + e2 + e3);
        m1[i] = e1 > h; m2[i] = e2 > h; m3[i] = e3 > h;
    }
    int ts[4] = {t.x, t.y, t.z, t.w};
    uchar4 u;
    u = make_uchar4(m1[0], m1[1], m1[2], m1[3]);
    *(uchar4*)(g_mask + (size_t)(b * 3 + 0) * NVOX + vbase) = u;
    u = make_uchar4(m2[0], m2[1], m2[2], m2[3]);
    *(uchar4*)(g_mask + (size_t)(b * 3 + 1) * NVOX + vbase) = u;
    u = make_uchar4(m3[0], m3[1], m3[2], m3[3]);
    *(uchar4*)(g_mask + (size_t)(b * 3 + 2) * NVOX + vbase) = u;
    u = make_uchar4(ts[0] == 1, ts[1] == 1, ts[2] == 1, ts[3] == 1);
    *(uchar4*)(g_mask + (size_t)(6 + b * 3 + 0) * NVOX + vbase) = u;
    u = make_uchar4(ts[0] == 2, ts[1] == 2, ts[2] == 2, ts[3] == 2);
    *(uchar4*)(g_mask + (size_t)(6 + b * 3 + 1) * NVOX + vbase) = u;
    u = make_uchar4(ts[0] == 3, ts[1] == 3, ts[2] == 3, ts[3] == 3);
    *(uchar4*)(g_mask + (size_t)(6 + b * 3 + 2) * NVOX + vbase) = u;
}

// Tiled init + local CC. Tile = full-x rows, 8y x 8z. Block 256 threads.
// grid: (128 tiles, 36 problems)
// p<12: mask CC ; 12..23: eroded-mask CC ; 24..35: background CC
__global__ void __launch_bounds__(256) k_local() {
    __shared__ u32 mb[10][10][4];   // mask bitmaps, +1 halo each side (y,z)
    __shared__ u32 ob[64][4];       // occupancy bitmaps for the 64 tile rows
    __shared__ int lab[TILE_VOX];   // 32 KB local labels

    int tid = threadIdx.x;
    int p = blockIdx.y;
    int ti = blockIdx.x;
    int z0 = (ti >> 4) * TZ;
    int y0 = (ti & 15) * TY;
    bool ero = (p >= 12) && (p < 24);
    int mi = (p < 12) ? p : (p < 24 ? p - 12 : p - 24);
    const u8* M = g_mask + (size_t)mi * NVOX;

    // zero bitmap (halo must be 0)
    for (int i = tid; i < 400; i += 256) ((u32*)mb)[i] = 0;
    __syncthreads();

    // load mask rows into bitmaps. 8 chunk-tasks per row (16 bytes each).
    int nrows = ero ? 100 : 64;
    for (int tk = tid; tk < nrows * 8; tk += 256) {
        int row = tk >> 3, ck = tk & 7;
        int zz, yy;
        if (ero) { zz = row / 10 - 1; yy = row % 10 - 1; }
        else     { zz = row >> 3;     yy = row & 7; }
        int z = z0 + zz, y = y0 + yy;
        if ((unsigned)z < DZ && (unsigned)y < HY) {
            uint4 q = *(const uint4*)(M + (size_t)z * HW + y * WX + ck * 16);
            u32 ws[4] = {q.x, q.y, q.z, q.w};
            u32 bits = 0;
            #pragma unroll
            for (int wi = 0; wi < 4; wi++)
                #pragma unroll
                for (int bi = 0; bi < 4; bi++)
                    bits |= ((ws[wi] >> (bi * 8)) & 1u) << (wi * 4 + bi);
            if (bits) atomicOr(&mb[zz + 1][yy + 1][ck >> 1], bits << ((ck & 1) * 16));
        }
    }
    __syncthreads();

    // occupancy bitmap per tile row: tid -> (row rr, word w)
    {
        int rr = tid >> 2, w = tid & 3;
        int zz = rr >> 3, yy = rr & 7;
        u32 m = mb[zz + 1][yy + 1][w];
        u32 o;
        if (p < 12)       o = m;
        else if (p >= 24) o = ~m;
        else {
            u32 ml = (m << 1) | (w > 0 ? (mb[zz + 1][yy + 1][w - 1] >> 31) : 0u);
            u32 mr = (m >> 1) | (w < 3 ? (mb[zz + 1][yy + 1][w + 1] << 31) : 0u);
            o = m & ml & mr &
                mb[zz + 1][yy][w] & mb[zz + 1][yy + 2][w] &
                mb[zz][yy + 1][w] & mb[zz + 2][yy + 1][w];
        }
        ob[rr][w] = o;
    }
    __syncthreads();

    // run-start local labels. tid -> (row rr, 32-x segment seg)
    int rr = tid >> 2, seg = tid & 3, xs = seg * 32;
    int base_li = rr * 128 + xs;
    u32 o = ob[rr][seg];
    {
        int run = trailing_run(ob[rr], xs);
        #pragma unroll
        for (int i = 0; i < 32; i++) {
            if ((o >> i) & 1u) { lab[base_li + i] = base_li + i - run; run++; }
            else               { lab[base_li + i] = -1; run = 0; }
        }
    }

    // zero reach flags for bg problems (this tile's region)
    if (p >= 24) {
        int z = z0 + (rr >> 3), y = y0 + (rr & 7);
        uint4* R = (uint4*)(g_reach + (size_t)(p - 24) * NVOX + (size_t)z * HW + y * WX + xs);
        R[0] = make_uint4(0, 0, 0, 0);
        R[1] = make_uint4(0, 0, 0, 0);
    }
    __syncthreads();

    // local unions (shared-memory UF), one per maximal run-overlap interval
    {
        int yy = rr & 7, zz = rr >> 3;
        if (yy > 0) {
            u32 up = ob[rr - 1][seg];
            u32 pair = o & up;
            if (pair) {
                u32 carry = (seg > 0) ? ((ob[rr][seg - 1] & ob[rr - 1][seg - 1]) >> 31) : 0u;
                u32 starts = pair & ~((pair << 1) | carry);
                while (starts) {
                    int b = __ffs(starts) - 1; starts &= starts - 1;
                    uf_union(lab, base_li + b, base_li + b - 128);
                }
            }
        }
        if (zz > 0) {
            u32 pv = ob[rr - 8][seg];
            u32 pair = o & pv;
            if (pair) {
                u32 carry = (seg > 0) ? ((ob[rr][seg - 1] & ob[rr - 8][seg - 1]) >> 31) : 0u;
                u32 starts = pair & ~((pair << 1) | carry);
                while (starts) {
                    int b = __ffs(starts) - 1; starts &= starts - 1;
                    uf_union(lab, base_li + b, base_li + b - 1024);
                }
            }
        }
    }
    __syncthreads();

    // flatten locally + write global labels
    {
        int z = z0 + (rr >> 3), y = y0 + (rr & 7);
        int gbase = z * HW + y * WX + xs;
        int* Lg = g_L + (size_t)p * NVOX;
        #pragma unroll
        for (int i = 0; i < 32; i += 4) {
            int4 w4;
            int l;
            l = lab[base_li + i];
            if (l >= 0) { int rt = uf_find(lab, base_li + i);
                w4.x = (z0 + (rt >> 10)) * HW + (y0 + ((rt >> 7) & 7)) * WX + (rt & 127);
            } else w4.x = -1;
            l = lab[base_li + i + 1];
            if (l >= 0) { int rt = uf_find(lab, base_li + i + 1);
                w4.y = (z0 + (rt >> 10)) * HW + (y0 + ((rt >> 7) & 7)) * WX + (rt & 127);
            } else w4.y = -1;
            l = lab[base_li + i + 2];
            if (l >= 0) { int rt = uf_find(lab, base_li + i + 2);
                w4.z = (z0 + (rt >> 10)) * HW + (y0 + ((rt >> 7) & 7)) * WX + (rt & 127);
            } else w4.z = -1;
            l = lab[base_li + i + 3];
            if (l >= 0) { int rt = uf_find(lab, base_li + i + 3);
                w4.w = (z0 + (rt >> 10)) * HW + (y0 + ((rt >> 7) & 7)) * WX + (rt & 127);
            } else w4.w = -1;
            *(int4*)(Lg + gbase + i) = w4;
        }
    }
}

// Cross-tile boundary merges. 1856 boundary rows per problem; warp per row.
// grid: (232, 36) block 256
__global__ void k_bmerge() {
    int p = blockIdx.y;
    int* L = g_L + (size_t)p * NVOX;
    int wr = blockIdx.x * 8 + (threadIdx.x >> 5);
    int lane = threadIdx.x & 31;
    int v, dir;
    if (wr < 960) {            // y-boundaries: y in {8,...,120}, all z
        int z = wr / 15, y = (wr % 15 + 1) * 8;
        v = z * HW + y * WX + lane * 4;
        dir = -WX;
    } else {                   // z-boundaries: z in {8,...,56}, all y
        int rz = wr - 960;
        int y = rz / 7, z = (rz % 7 + 1) * 8;
        v = z * HW + y * WX + lane * 4;
        dir = -HW;
    }
    int4 a = *(const int4*)(L + v);
    int4 u = *(const int4*)(L + v + dir);
    int la[4] = {a.x, a.y, a.z, a.w};
    int lu[4] = {u.x, u.y, u.z, u.w};
    int pa = -2, pu = -2;
    #pragma unroll
    for (int i = 0; i < 4; i++) {
        if (la[i] >= 0 && lu[i] >= 0 && (la[i] != pa || lu[i] != pu)) {
            uf_union(L, v + i, v + i + dir);
            pa = la[i]; pu = lu[i];
        }
    }
}

// Mark bg components touching the volume border (find on the fly).
// grid:(NVOX/1024, 12) block 256
__global__ void k_border() {
    int p = blockIdx.y;
    int vbase = (blockIdx.x * 256 + threadIdx.x) * 4;
    int x0 = vbase & (WX - 1);
    int y = (vbase >> 7) & (HY - 1);
    int z = vbase >> 14;
    int* L = g_L + (size_t)(24 + p) * NVOX;
    u8* R = g_reach + (size_t)p * NVOX;
    bool grpB = (z == 0) || (z == DZ - 1) || (y == 0) || (y == HY - 1);
    if (grpB) {
        #pragma unroll
        for (int i = 0; i < 4; i++) {
            if (L[vbase + i] >= 0) R[uf_find(L, vbase + i)] = 1;
        }
    } else if (x0 == 0) {
        if (L[vbase] >= 0) R[uf_find(L, vbase)] = 1;
    } else if (x0 == WX - 4) {
        if (L[vbase + 3] >= 0) R[uf_find(L, vbase + 3)] = 1;
    }
}

// Count roots (p<24) / cavity voxels (p>=24).  grid:(NVOX/1024, 36) block 256
__global__ void k_count() {
    int p = blockIdx.y;
    int vbase = (blockIdx.x * 256 + threadIdx.x) * 4;
    int* L = g_L + (size_t)p * NVOX;
    int4 a = *(const int4*)(L + vbase);
    int c = 0;
    if (p < 24) {
        c = (a.x == vbase) + (a.y == vbase + 1) + (a.z == vbase + 2) + (a.w == vbase + 3);
    } else {
        const u8* R = g_reach + (size_t)(p - 24) * NVOX;
        if (a.x >= 0) c += (R[uf_find(L, vbase)] == 0);
        if (a.y >= 0) c += (R[uf_find(L, vbase + 1)] == 0);
        if (a.z >= 0) c += (R[uf_find(L, vbase + 2)] == 0);
        if (a.w >= 0) c += (R[uf_find(L, vbase + 3)] == 0);
    }
    #pragma unroll
    for (int off = 16; off > 0; off >>= 1)
        c += __shfl_down_sync(0xFFFFFFFFu, c, off);
    __shared__ int ssum;
    if (threadIdx.x == 0) ssum = 0;
    __syncthreads();
    if ((threadIdx.x & 31) == 0 && c) atomicAdd(&ssum, c);
    __syncthreads();
    if (threadIdx.x == 0 && ssum) atomicAdd(&g_cnt[p], ssum);
}

__device__ __forceinline__ int iabs_(int a) { return a < 0 ? -a : a; }
__device__ __forceinline__ int imax0_(int a) { return a > 0 ? a : 0; }

__global__ void k_final(float* __restrict__ out) {
    float tot = 0.0f;
    #pragma unroll
    for (int i = 0; i < 6; i++) {
        int pb0 = g_cnt[i],      tb0 = g_cnt[i + 6];
        int pbe = g_cnt[12 + i], tbe = g_cnt[12 + i + 6];
        int pcv = g_cnt[24 + i], tcv = g_cnt[24 + i + 6];
        int pb1 = imax0_(pb0 - pbe), tb1 = imax0_(tb0 - tbe);
        int pb2 = pcv / 100,         tb2 = tcv / 100;
        tot += (float)(iabs_(pb0 - tb0) + iabs_(pb1 - tb1) + iabs_(pb2 - tb2));
    }
    out[0] = 0.1f * tot / 6.0f;
}

// ---------------- launch ----------------
extern "C" void kernel_launch(void* const* d_in, const int* in_sizes, int n_in,
                              void* d_out, int out_size) {
    const float* pred   = (const float*)d_in[0];
    const int*   target = (const int*)d_in[1];
    float*       out    = (float*)d_out;

    k_zero_counters<<<1, 64>>>();
    k_masks<<<dim3(NVOX / 1024, 2), 256>>>(pred, target);
    k_local<<<dim3(128, NPROB), 256>>>();
    k_bmerge<<<dim3(232, NPROB), 256>>>();
    k_border<<<dim3(NVOX / 1024, 12), 256>>>();
    k_count<<<dim3(NVOX / 1024, NPROB), 256>>>();
    k_final<<<1, 1>>>(out);
}

// round 7
// speedup vs baseline: 1.3027x; 1.3027x over previous
#include <cuda_runtime.h>
#include <cuda_bf16.h>
#include <stdint.h>
#include <math.h>

// Volume: D=64, H=128, W=128 ; B=2, C=4  (fixed shapes)
#define DZ 64
#define HY 128
#define WX 128
#define HW (HY * WX)
#define NVOX (DZ * HY * WX)   // 1,048,576
#define NROWS 8192            // DZ*HY rows of 128 voxels
#define NMASK 12
#define NPROB 36
#define RCAP (NROWS * 64)     // max runs per problem = 524288

typedef unsigned int u32;
typedef unsigned long long u64;
typedef unsigned char u8;

// Scratch (device globals)
__device__ uint4 g_mbits[NMASK][NROWS];   // mask bitmaps, 16B/row  (1.5 MB)
__device__ uint4 g_ebits[NMASK][NROWS];   // eroded bitmaps         (1.5 MB)
__device__ int   g_P[(size_t)NPROB * RCAP];  // run-level UF parents (75.5 MB, sparsely touched)
__device__ u8    g_R[(size_t)NMASK * RCAP];  // bg run border-reach flags (6.3 MB, sparse)
__device__ int   g_cnt[NPROB];

// ---------------- 128-bit row helpers ----------------
struct B128 { u64 lo, hi; };

__device__ __forceinline__ B128 b_load(const uint4* arr, int row) {
    uint4 q = arr[row];
    B128 r;
    r.lo = (u64)q.x | ((u64)q.y << 32);
    r.hi = (u64)q.z | ((u64)q.w << 32);
    return r;
}
__device__ __forceinline__ void b_store(uint4* arr, int row, B128 v) {
    arr[row] = make_uint4((u32)v.lo, (u32)(v.lo >> 32), (u32)v.hi, (u32)(v.hi >> 32));
}
__device__ __forceinline__ B128 b_and(B128 a, B128 b) { return {a.lo & b.lo, a.hi & b.hi}; }
__device__ __forceinline__ B128 b_not(B128 a) { return {~a.lo, ~a.hi}; }
__device__ __forceinline__ B128 b_shl1(B128 a) { return {a.lo << 1, (a.hi << 1) | (a.lo >> 63)}; }
__device__ __forceinline__ B128 b_shr1(B128 a) { return {(a.lo >> 1) | (a.hi << 63), a.hi >> 1}; }
__device__ __forceinline__ bool b_any(B128 a) { return (a.lo | a.hi) != 0ULL; }
__device__ __forceinline__ int  b_pop(B128 a) { return __popcll(a.lo) + __popcll(a.hi); }
// run starts: bits set where occ is set and bit below is clear
__device__ __forceinline__ B128 b_starts(B128 o) { B128 s = b_shl1(o); return {o.lo & ~s.lo, o.hi & ~s.hi}; }
// popcount of bits <= position b
__device__ __forceinline__ int b_pople(B128 s, int b) {
    if (b < 64) {
        u64 m = (b == 63) ? ~0ULL : ((1ULL << (b + 1)) - 1ULL);
        return __popcll(s.lo & m);
    }
    int bb = b - 64;
    u64 m = (bb == 63) ? ~0ULL : ((1ULL << (bb + 1)) - 1ULL);
    return __popcll(s.lo) + __popcll(s.hi & m);
}
__device__ __forceinline__ int cto64(u64 x) {  // count trailing ones
    u64 inv = ~x;
    return inv ? (__ffsll((long long)inv) - 1) : 64;
}
// length of the run of ones starting at bit b
__device__ __forceinline__ int b_runlen(B128 o, int b) {
    B128 sh;
    if (b == 0) sh = o;
    else if (b < 64) { sh.lo = (o.lo >> b) | (o.hi << (64 - b)); sh.hi = o.hi >> b; }
    else { sh.lo = o.hi >> (b - 64); sh.hi = 0; }
    int c = cto64(sh.lo);
    if (c == 64) c += cto64(sh.hi);
    return c;
}

// ---------------- union-find on run table ----------------
__device__ __forceinline__ int uf_find(int* P, int x) {
    while (true) {
        int p = P[x];
        if (p == x) return x;
        int gp = P[p];
        if (gp != p) P[x] = gp;
        x = gp;
    }
}
__device__ __forceinline__ void uf_union(int* P, int a, int b) {
    while (true) {
        a = uf_find(P, a);
        b = uf_find(P, b);
        if (a == b) return;
        if (a > b) { int t = a; a = b; b = t; }
        int old = atomicMin(&P[b], a);
        if (old == b) return;
        b = old;
    }
}

// occupancy for problem p, row r
__device__ __forceinline__ B128 get_occ(int p, int row) {
    if (p < 12) return b_load(g_mbits[p], row);
    if (p < 24) return b_load(g_ebits[p - 12], row);
    return b_not(b_load(g_mbits[p - 24], row));
}

// ---------------- kernels ----------------

__global__ void k_zero_counters() {
    int i = threadIdx.x;
    if (i < NPROB) g_cnt[i] = 0;
}

// Warp per (batch,row): softmax+threshold -> 6 bitmap rows.  grid 2048 x 256
__global__ void k_masks(const float* __restrict__ pred, const int* __restrict__ target) {
    int gw = blockIdx.x * 8 + (threadIdx.x >> 5);
    int lane = threadIdx.x & 31;
    int b = gw >> 13;            // 8192 rows per batch
    int row = gw & (NROWS - 1);
    int v = row * WX + lane * 4;

    const float* pp = pred + (size_t)b * 4 * NVOX + v;
    float4 a0 = *(const float4*)(pp);
    float4 a1 = *(const float4*)(pp + NVOX);
    float4 a2 = *(const float4*)(pp + 2 * NVOX);
    float4 a3 = *(const float4*)(pp + 3 * NVOX);
    int4 t = *(const int4*)(target + (size_t)b * NVOX + v);

    float x0s[4] = {a0.x, a0.y, a0.z, a0.w};
    float x1s[4] = {a1.x, a1.y, a1.z, a1.w};
    float x2s[4] = {a2.x, a2.y, a2.z, a2.w};
    float x3s[4] = {a3.x, a3.y, a3.z, a3.w};
    u32 nib[6] = {0, 0, 0, 0, 0, 0};
    #pragma unroll
    for (int i = 0; i < 4; i++) {
        float m = fmaxf(fmaxf(x0s[i], x1s[i]), fmaxf(x2s[i], x3s[i]));
        float e0 = expf(x0s[i] - m), e1 = expf(x1s[i] - m);
        float e2 = expf(x2s[i] - m), e3 = expf(x3s[i] - m);
        float h = 0.5f * (e0 + e1 + e2 + e3);
        nib[0] |= (e1 > h) << i;
        nib[1] |= (e2 > h) << i;
        nib[2] |= (e3 > h) << i;
    }
    int ts[4] = {t.x, t.y, t.z, t.w};
    #pragma unroll
    for (int i = 0; i < 4; i++) {
        nib[3] |= (ts[i] == 1) << i;
        nib[4] |= (ts[i] == 2) << i;
        nib[5] |= (ts[i] == 3) << i;
    }
    int sh = (lane & 7) * 4;
    int widx = lane >> 3;
    #pragma unroll
    for (int k = 0; k < 6; k++) {
        u32 seg = nib[k] << sh;
        seg |= __shfl_xor_sync(0xFFFFFFFFu, seg, 1);
        seg |= __shfl_xor_sync(0xFFFFFFFFu, seg, 2);
        seg |= __shfl_xor_sync(0xFFFFFFFFu, seg, 4);
        if ((lane & 7) == 0) {
            int mi = (k < 3) ? (b * 3 + k) : (6 + b * 3 + (k - 3));
            ((u32*)&g_mbits[mi][row])[widx] = seg;
        }
    }
}

// Erosion on bitmaps.  grid (32,12) x 256 ; thread per row
__global__ void k_erode() {
    int row = blockIdx.x * 256 + threadIdx.x;
    int mi = blockIdx.y;
    int y = row & (HY - 1);
    int z = row >> 7;
    B128 e;
    if (y == 0 || y == HY - 1 || z == 0 || z == DZ - 1) {
        e.lo = 0; e.hi = 0;
    } else {
        B128 m  = b_load(g_mbits[mi], row);
        B128 up = b_load(g_mbits[mi], row - 1);
        B128 dn = b_load(g_mbits[mi], row + 1);
        B128 fr = b_load(g_mbits[mi], row - HY);
        B128 bk = b_load(g_mbits[mi], row + HY);
        B128 ml = b_shl1(m), mr = b_shr1(m);
        e.lo = m.lo & ml.lo & mr.lo & up.lo & dn.lo & fr.lo & bk.lo;
        e.hi = m.hi & ml.hi & mr.hi & up.hi & dn.hi & fr.hi & bk.hi;
    }
    b_store(g_ebits[mi], row, e);
}

// Init run-table parents.  grid (32,36) x 256 ; thread per row
__global__ void k_runinit() {
    int row = blockIdx.x * 256 + threadIdx.x;
    int p = blockIdx.y;
    B128 occ = get_occ(p, row);
    B128 st = b_starts(occ);
    int n = b_pop(st);
    int base = row * 64;
    int* P = g_P + (size_t)p * RCAP;
    for (int k = 0; k < n; k++) P[base + k] = base + k;
    if (p >= 24) {
        u8* R = g_R + (size_t)(p - 24) * RCAP;
        for (int k = 0; k < n; k++) R[base + k] = 0;
    }
}

// Merge adjacent rows (y and z neighbors), one union per overlap interval.
// grid (64,36) x 256 ; thread per row-pair (16192 pairs/problem)
__global__ void k_merge() {
    int t = blockIdx.x * 256 + threadIdx.x;
    if (t >= 16192) return;
    int p = blockIdx.y;
    int rowA, rowB;
    if (t < 8128) {               // y-pairs: z in [0,64), y in [1,128)
        int z = t / 127, y = t % 127 + 1;
        rowA = z * HY + y; rowB = rowA - 1;
    } else {                      // z-pairs: z in [1,64), y in [0,128)
        int s = t - 8128;
        int z = s / 128 + 1, y = s % 128;
        rowA = z * HY + y; rowB = rowA - HY;
    }
    B128 oA = get_occ(p, rowA);
    B128 oB = get_occ(p, rowB);
    B128 pr = b_and(oA, oB);
    if (!b_any(pr)) return;
    B128 ps = b_starts(pr);
    B128 sA = b_starts(oA);
    B128 sB = b_starts(oB);
    int baseA = rowA * 64, baseB = rowB * 64;
    int* P = g_P + (size_t)p * RCAP;
    u64 w = ps.lo;
    while (w) {
        int b = __ffsll((long long)w) - 1; w &= w - 1;
        uf_union(P, baseA + b_pople(sA, b) - 1, baseB + b_pople(sB, b) - 1);
    }
    w = ps.hi;
    while (w) {
        int b = __ffsll((long long)w) - 1; w &= w - 1;
        int bb = b + 64;
        uf_union(P, baseA + b_pople(sA, bb) - 1, baseB + b_pople(sB, bb) - 1);
    }
}

// Mark bg components reaching the volume border.  grid (32,12) x 256
__global__ void k_bordermark() {
    int row = blockIdx.x * 256 + threadIdx.x;
    int pb = blockIdx.y;
    int p = 24 + pb;
    int y = row & (HY - 1);
    int z = row >> 7;
    B128 occ = get_occ(p, row);
    if (!b_any(occ)) return;
    int base = row * 64;
    int* P = g_P + (size_t)p * RCAP;
    u8* R = g_R + (size_t)pb * RCAP;
    bool borderrow = (z == 0) || (z == DZ - 1) || (y == 0) || (y == HY - 1);
    if (borderrow) {
        int n = b_pop(b_starts(occ));
        for (int k = 0; k < n; k++) R[uf_find(P, base + k)] = 1;
    } else {
        if (occ.lo & 1ULL) R[uf_find(P, base)] = 1;
        if (occ.hi >> 63) {
            int n = b_pop(b_starts(occ));
            R[uf_find(P, base + n - 1)] = 1;
        }
    }
}

// Count roots (p<24) / cavity voxels (p>=24).  grid (32,36) x 256
__global__ void k_count() {
    int row = blockIdx.x * 256 + threadIdx.x;
    int p = blockIdx.y;
    B128 occ = get_occ(p, row);
    int base = row * 64;
    int* P = g_P + (size_t)p * RCAP;
    int c = 0;
    if (b_any(occ)) {
        B128 st = b_starts(occ);
        if (p < 24) {
            int n = b_pop(st);
            for (int k = 0; k < n; k++) c += (P[base + k] == base + k);
        } else {
            const u8* R = g_R + (size_t)(p - 24) * RCAP;
            int k = 0;
            u64 w = st.lo;
            while (w) {
                int b = __ffsll((long long)w) - 1; w &= w - 1;
                if (!R[uf_find(P, base + k)]) c += b_runlen(occ, b);
                k++;
            }
            w = st.hi;
            while (w) {
                int b = __ffsll((long long)w) - 1; w &= w - 1;
                if (!R[uf_find(P, base + k)]) c += b_runlen(occ, b + 64);
                k++;
            }
        }
    }
    #pragma unroll
    for (int off = 16; off > 0; off >>= 1)
        c += __shfl_down_sync(0xFFFFFFFFu, c, off);
    __shared__ int ssum;
    if (threadIdx.x == 0) ssum = 0;
    __syncthreads();
    if ((threadIdx.x & 31) == 0 && c) atomicAdd(&ssum, c);
    __syncthreads();
    if (threadIdx.x == 0 && ssum) atomicAdd(&g_cnt[p], ssum);
}

__device__ __forceinline__ int iabs_(int a) { return a < 0 ? -a : a; }
__device__ __forceinline__ int imax0_(int a) { return a > 0 ? a : 0; }

__global__ void k_final(float* __restrict__ out) {
    float tot = 0.0f;
    #pragma unroll
    for (int i = 0; i < 6; i++) {
        int pb0 = g_cnt[i],      tb0 = g_cnt[i + 6];
        int pbe = g_cnt[12 + i], tbe = g_cnt[12 + i + 6];
        int pcv = g_cnt[24 + i], tcv = g_cnt[24 + i + 6];
        int pb1 = imax0_(pb0 - pbe), tb1 = imax0_(tb0 - tbe);
        int pb2 = pcv / 100,         tb2 = tcv / 100;
        tot += (float)(iabs_(pb0 - tb0) + iabs_(pb1 - tb1) + iabs_(pb2 - tb2));
    }
    out[0] = 0.1f * tot / 6.0f;
}

// ---------------- launch ----------------
extern "C" void kernel_launch(void* const* d_in, const int* in_sizes, int n_in,
                              void* d_out, int out_size) {
    const float* pred   = (const float*)d_in[0];
    const int*   target = (const int*)d_in[1];
    float*       out    = (float*)d_out;

    k_zero_counters<<<1, 64>>>();
    k_masks<<<2048, 256>>>(pred, target);
    k_erode<<<dim3(32, 12), 256>>>();
    k_runinit<<<dim3(32, NPROB), 256>>>();
    k_merge<<<dim3(64, NPROB), 256>>>();
    k_bordermark<<<dim3(32, 12), 256>>>();
    k_count<<<dim3(32, NPROB), 256>>>();
    k_final<<<1, 1>>>(out);
}

// round 9
// speedup vs baseline: 2.5093x; 1.9262x over previous
#include <cuda_runtime.h>
#include <cuda_bf16.h>
#include <stdint.h>
#include <math.h>

// Volume: D=64, H=128, W=128 ; B=2, C=4  (fixed shapes)
#define DZ 64
#define HY 128
#define WX 128
#define HW (HY * WX)
#define NVOX (DZ * HY * WX)   // 1,048,576
#define NROWS 8192            // DZ*HY rows of 128 voxels
#define NMASK 12
#define NPROB 36
#define RCAP (NROWS * 64)     // max runs per problem = 524288

typedef unsigned int u32;
typedef unsigned long long u64;
typedef unsigned char u8;

// Scratch (device globals)
__device__ uint4 g_mbits[NMASK][NROWS];      // mask bitmaps, 16B/row  (1.5 MB)
__device__ uint4 g_ebits[NMASK][NROWS];      // eroded bitmaps         (1.5 MB)
__device__ int   g_P[(size_t)NPROB * RCAP];  // run-level UF parents (75.5 MB; sentinel-init)
__device__ u8    g_R[(size_t)NMASK * RCAP];  // bg run border-reach flags (6.3 MB)
__device__ int   g_cnt[NPROB];

// ---------------- 128-bit row helpers ----------------
struct B128 { u64 lo, hi; };

__device__ __forceinline__ B128 b_load(const uint4* arr, int row) {
    uint4 q = arr[row];
    B128 r;
    r.lo = (u64)q.x | ((u64)q.y << 32);
    r.hi = (u64)q.z | ((u64)q.w << 32);
    return r;
}
__device__ __forceinline__ void b_store(uint4* arr, int row, B128 v) {
    arr[row] = make_uint4((u32)v.lo, (u32)(v.lo >> 32), (u32)v.hi, (u32)(v.hi >> 32));
}
__device__ __forceinline__ B128 b_and(B128 a, B128 b) { return {a.lo & b.lo, a.hi & b.hi}; }
__device__ __forceinline__ B128 b_not(B128 a) { return {~a.lo, ~a.hi}; }
__device__ __forceinline__ B128 b_shl1(B128 a) { return {a.lo << 1, (a.hi << 1) | (a.lo >> 63)}; }
__device__ __forceinline__ B128 b_shr1(B128 a) { return {(a.lo >> 1) | (a.hi << 63), a.hi >> 1}; }
__device__ __forceinline__ bool b_any(B128 a) { return (a.lo | a.hi) != 0ULL; }
__device__ __forceinline__ int  b_pop(B128 a) { return __popcll(a.lo) + __popcll(a.hi); }
// run starts: bits set where occ is set and bit below is clear
__device__ __forceinline__ B128 b_starts(B128 o) { B128 s = b_shl1(o); return {o.lo & ~s.lo, o.hi & ~s.hi}; }
// popcount of start bits strictly below global bit position b (b in [0,128])
__device__ __forceinline__ int b_popbelow(B128 s, int b) {
    if (b == 0) return 0;
    if (b <= 64) {
        u64 m = (b == 64) ? ~0ULL : ((1ULL << b) - 1ULL);
        return __popcll(s.lo & m);
    }
    int bb = b - 64;
    u64 m = (bb >= 64) ? ~0ULL : ((1ULL << bb) - 1ULL);
    return __popcll(s.lo) + __popcll(s.hi & m);
}
__device__ __forceinline__ int cto64(u64 x) {  // count trailing ones
    u64 inv = ~x;
    return inv ? (__ffsll((long long)inv) - 1) : 64;
}
// length of the run of ones starting at bit b
__device__ __forceinline__ int b_runlen(B128 o, int b) {
    B128 sh;
    if (b == 0) sh = o;
    else if (b < 64) { sh.lo = (o.lo >> b) | (o.hi << (64 - b)); sh.hi = o.hi >> b; }
    else { sh.lo = o.hi >> (b - 64); sh.hi = 0; }
    int c = cto64(sh.lo);
    if (c == 64) c += cto64(sh.hi);
    return c;
}

// ---------------- union-find (sentinel roots: P[x] >= RCAP means root) -----
__device__ __forceinline__ int uf_find(int* P, int x) {
    while (true) {
        int p = P[x];
        if (p >= RCAP) return x;
        int gp = P[p];
        if (gp >= RCAP) return p;
        P[x] = gp;   // path halving
        x = gp;
    }
}
__device__ __forceinline__ void uf_union(int* P, int a, int b) {
    while (true) {
        a = uf_find(P, a);
        b = uf_find(P, b);
        if (a == b) return;
        if (a > b) { int t = a; a = b; b = t; }
        int old = atomicMin(&P[b], a);
        if (old >= RCAP || old == b) return;   // b was a root -> linked
        b = old;                                // lost race: continue from displaced parent
    }
}

// occupancy for problem p, row r
__device__ __forceinline__ B128 get_occ(int p, int row) {
    if (p < 12) return b_load(g_mbits[p], row);
    if (p < 24) return b_load(g_ebits[p - 12], row);
    return b_not(b_load(g_mbits[p - 24], row));
}

// ---------------- kernels ----------------

// Streaming sentinel-init: g_P <- 0x7F7F7F7F, g_R <- 0, g_cnt <- 0.
// grid-stride int4 stores.  grid 2048 x 256
__global__ void k_initP() {
    const u32 SEN = 0x7F7F7F7Fu;
    size_t nP4 = (size_t)NPROB * RCAP / 4;     // int4 count over g_P
    uint4* P4 = (uint4*)g_P;
    uint4 sv = make_uint4(SEN, SEN, SEN, SEN);
    size_t stride = (size_t)gridDim.x * blockDim.x;
    for (size_t i = blockIdx.x * (size_t)blockDim.x + threadIdx.x; i < nP4; i += stride)
        P4[i] = sv;
    size_t nR4 = (size_t)NMASK * RCAP / 16;    // uint4 count over g_R
    uint4* R4 = (uint4*)g_R;
    uint4 zv = make_uint4(0, 0, 0, 0);
    for (size_t i = blockIdx.x * (size_t)blockDim.x + threadIdx.x; i < nR4; i += stride)
        R4[i] = zv;
    if (blockIdx.x == 0 && threadIdx.x < NPROB) g_cnt[threadIdx.x] = 0;
}

// Warp per (batch,row): softmax+threshold -> 6 bitmap rows.  grid 2048 x 256
__global__ void k_masks(const float* __restrict__ pred, const int* __restrict__ target) {
    int gw = blockIdx.x * 8 + (threadIdx.x >> 5);
    int lane = threadIdx.x & 31;
    int b = gw >> 13;            // 8192 rows per batch
    int row = gw & (NROWS - 1);
    int v = row * WX + lane * 4;

    const float* pp = pred + (size_t)b * 4 * NVOX + v;
    float4 a0 = *(const float4*)(pp);
    float4 a1 = *(const float4*)(pp + NVOX);
    float4 a2 = *(const float4*)(pp + 2 * NVOX);
    float4 a3 = *(const float4*)(pp + 3 * NVOX);
    int4 t = *(const int4*)(target + (size_t)b * NVOX + v);

    float x0s[4] = {a0.x, a0.y, a0.z, a0.w};
    float x1s[4] = {a1.x, a1.y, a1.z, a1.w};
    float x2s[4] = {a2.x, a2.y, a2.z, a2.w};
    float x3s[4] = {a3.x, a3.y, a3.z, a3.w};
    u32 nib[6] = {0, 0, 0, 0, 0, 0};
    #pragma unroll
    for (int i = 0; i < 4; i++) {
        float m = fmaxf(fmaxf(x0s[i], x1s[i]), fmaxf(x2s[i], x3s[i]));
        float e0 = expf(x0s[i] - m), e1 = expf(x1s[i] - m);
        float e2 = expf(x2s[i] - m), e3 = expf(x3s[i] - m);
        float h = 0.5f * (e0 + e1 + e2 + e3);
        nib[0] |= (e1 > h) << i;
        nib[1] |= (e2 > h) << i;
        nib[2] |= (e3 > h) << i;
    }
    int ts[4] = {t.x, t.y, t.z, t.w};
    #pragma unroll
    for (int i = 0; i < 4; i++) {
        nib[3] |= (ts[i] == 1) << i;
        nib[4] |= (ts[i] == 2) << i;
        nib[5] |= (ts[i] == 3) << i;
    }
    int sh = (lane & 7) * 4;
    int widx = lane >> 3;
    #pragma unroll
    for (int k = 0; k < 6; k++) {
        u32 seg = nib[k] << sh;
        seg |= __shfl_xor_sync(0xFFFFFFFFu, seg, 1);
        seg |= __shfl_xor_sync(0xFFFFFFFFu, seg, 2);
        seg |= __shfl_xor_sync(0xFFFFFFFFu, seg, 4);
        if ((lane & 7) == 0) {
            int mi = (k < 3) ? (b * 3 + k) : (6 + b * 3 + (k - 3));
            ((u32*)&g_mbits[mi][row])[widx] = seg;
        }
    }
}

// Erosion on bitmaps.  grid (32,12) x 256 ; thread per row
__global__ void k_erode() {
    int row = blockIdx.x * 256 + threadIdx.x;
    int mi = blockIdx.y;
    int y = row & (HY - 1);
    int z = row >> 7;
    B128 e;
    if (y == 0 || y == HY - 1 || z == 0 || z == DZ - 1) {
        e.lo = 0; e.hi = 0;
    } else {
        B128 m  = b_load(g_mbits[mi], row);
        B128 up = b_load(g_mbits[mi], row - 1);
        B128 dn = b_load(g_mbits[mi], row + 1);
        B128 fr = b_load(g_mbits[mi], row - HY);
        B128 bk = b_load(g_mbits[mi], row + HY);
        B128 ml = b_shl1(m), mr = b_shr1(m);
        e.lo = m.lo & ml.lo & mr.lo & up.lo & dn.lo & fr.lo & bk.lo;
        e.hi = m.hi & ml.hi & mr.hi & up.hi & dn.hi & fr.hi & bk.hi;
    }
    b_store(g_ebits[mi], row, e);
}

// Merge adjacent rows (y and z neighbors), one union per overlap interval.
// 2 threads per row-pair (one per 64-bit half).  grid (127,36) x 256
__global__ void k_merge() {
    int t = blockIdx.x * 256 + threadIdx.x;
    if (t >= 16192 * 2) return;
    int pairid = t >> 1, half = t & 1;
    int p = blockIdx.y;
    int rowA, rowB;
    if (pairid < 8128) {          // y-pairs: z in [0,64), y in [1,128)
        int z = pairid / 127, y = pairid % 127 + 1;
        rowA = z * HY + y; rowB = rowA - 1;
    } else {                      // z-pairs: z in [1,64), y in [0,128)
        int s = pairid - 8128;
        int z = s / 128 + 1, y = s % 128;
        rowA = z * HY + y; rowB = rowA - HY;
    }
    B128 oA = get_occ(p, rowA);
    B128 oB = get_occ(p, rowB);
    B128 pr = b_and(oA, oB);
    B128 ps = b_starts(pr);
    u64 w = half ? ps.hi : ps.lo;
    if (!w) return;
    B128 sA = b_starts(oA);
    B128 sB = b_starts(oB);
    int baseA = rowA * 64, baseB = rowB * 64;
    int boff = half * 64;
    int* P = g_P + (size_t)p * RCAP;
    while (w) {
        int b = __ffsll((long long)w) - 1; w &= w - 1;
        int gb = b + boff;
        uf_union(P, baseA + b_popbelow(sA, gb + 1) - 1,
                    baseB + b_popbelow(sB, gb + 1) - 1);
    }
}

// Mark bg components reaching the volume border. 4 threads/row.
// grid (128,12) x 256
__global__ void k_bordermark() {
    int t = blockIdx.x * 256 + threadIdx.x;
    int row = t >> 2, w = t & 3;
    int pb = blockIdx.y;
    int p = 24 + pb;
    int y = row & (HY - 1);
    int z = row >> 7;
    B128 occ = get_occ(p, row);
    if (!b_any(occ)) return;
    int base = row * 64;
    int* P = g_P + (size_t)p * RCAP;
    u8* R = g_R + (size_t)pb * RCAP;
    B128 st = b_starts(occ);
    bool borderrow = (z == 0) || (z == DZ - 1) || (y == 0) || (y == HY - 1);
    if (borderrow) {
        u32 stw = (w < 2) ? (u32)(st.lo >> (w * 32)) : (u32)(st.hi >> ((w - 2) * 32));
        if (!stw) return;
        int k = b_popbelow(st, w * 32);
        while (stw) {
            stw &= stw - 1;
            R[uf_find(P, base + k)] = 1;
            k++;
        }
    } else {
        if (w == 0) {
            if (occ.lo & 1ULL) R[uf_find(P, base)] = 1;
        } else if (w == 3) {
            if (occ.hi >> 63) R[uf_find(P, base + b_pop(st) - 1)] = 1;
        }
    }
}

// Count roots (p<24) / cavity voxels (p>=24). 4 threads/row.
// grid (128,36) x 256
__global__ void k_count() {
    int t = blockIdx.x * 256 + threadIdx.x;
    int row = t >> 2, w = t & 3;
    int p = blockIdx.y;
    B128 occ = get_occ(p, row);
    int c = 0;
    if (b_any(occ)) {
        B128 st = b_starts(occ);
        u32 stw = (w < 2) ? (u32)(st.lo >> (w * 32)) : (u32)(st.hi >> ((w - 2) * 32));
        if (stw) {
            int base = row * 64;
            int* P = g_P + (size_t)p * RCAP;
            int k = b_popbelow(st, w * 32);
            if (p < 24) {
                while (stw) {
                    stw &= stw - 1;
                    c += (P[base + k] >= RCAP);
                    k++;
                }
            } else {
                const u8* R = g_R + (size_t)(p - 24) * RCAP;
                int boff = w * 32;
                while (stw) {
                    int b = __ffs(stw) - 1; stw &= stw - 1;
                    if (!R[uf_find(P, base + k)]) c += b_runlen(occ, b + boff);
                    k++;
                }
            }
        }
    }
    #pragma unroll
    for (int off = 16; off > 0; off >>= 1)
        c += __shfl_down_sync(0xFFFFFFFFu, c, off);
    __shared__ int ssum;
    if (threadIdx.x == 0) ssum = 0;
    __syncthreads();
    if ((threadIdx.x & 31) == 0 && c) atomicAdd(&ssum, c);
    __syncthreads();
    if (threadIdx.x == 0 && ssum) atomicAdd(&g_cnt[p], ssum);
}

__device__ __forceinline__ int iabs_(int a) { return a < 0 ? -a : a; }
__device__ __forceinline__ int imax0_(int a) { return a > 0 ? a : 0; }

__global__ void k_final(float* __restrict__ out) {
    float tot = 0.0f;
    #pragma unroll
    for (int i = 0; i < 6; i++) {
        int pb0 = g_cnt[i],      tb0 = g_cnt[i + 6];
        int pbe = g_cnt[12 + i], tbe = g_cnt[12 + i + 6];
        int pcv = g_cnt[24 + i], tcv = g_cnt[24 + i + 6];
        int pb1 = imax0_(pb0 - pbe), tb1 = imax0_(tb0 - tbe);
        int pb2 = pcv / 100,         tb2 = tcv / 100;
        tot += (float)(iabs_(pb0 - tb0) + iabs_(pb1 - tb1) + iabs_(pb2 - tb2));
    }
    out[0] = 0.1f * tot / 6.0f;
}

// ---------------- launch ----------------
extern "C" void kernel_launch(void* const* d_in, const int* in_sizes, int n_in,
                              void* d_out, int out_size) {
    const float* pred   = (const float*)d_in[0];
    const int*   target = (const int*)d_in[1];
    float*       out    = (float*)d_out;

    k_initP<<<2048, 256>>>();
    k_masks<<<2048, 256>>>(pred, target);
    k_erode<<<dim3(32, 12), 256>>>();
    k_merge<<<dim3(127, NPROB), 256>>>();
    k_bordermark<<<dim3(128, 12), 256>>>();
    k_count<<<dim3(128, NPROB), 256>>>();
    k_final<<<1, 1>>>(out);
}

// round 12
// speedup vs baseline: 3.3762x; 1.3455x over previous
#include <cuda_runtime.h>
#include <cuda_bf16.h>
#include <stdint.h>
#include <math.h>

// Volume: D=64, H=128, W=128 ; B=2, C=4  (fixed shapes)
#define DZ 64
#define HY 128
#define WX 128
#define HW (HY * WX)
#define NVOX (DZ * HY * WX)   // 1,048,576
#define NROWS 8192            // DZ*HY rows of 128 voxels
#define NMASK 12
#define NPROB 36
#define RCAP (NROWS * 64)     // run slots per problem = 524288
#define PRUN 8192             // run slots per z-plane (128 rows * 64)
#define SEN  0x7F7F7F7F       // global sentinel (>= RCAP -> root)
#define LSEN 0x7FFFFFFF       // plane-local sentinel (>= PRUN -> root)

typedef unsigned int u32;
typedef unsigned long long u64;
typedef unsigned char u8;

// Scratch (device globals)
__device__ uint4 g_mbits[NMASK][NROWS];      // mask bitmaps, 16B/row
__device__ uint4 g_ebits[NMASK][NROWS];      // eroded bitmaps
__device__ int   g_P[(size_t)NPROB * RCAP];  // run-level UF parents (written by k_plane)
__device__ u8    g_R[(size_t)NMASK * RCAP];  // bg run border-reach flags
__device__ int   g_cnt[NPROB];

// ---------------- 128-bit row helpers ----------------
struct B128 { u64 lo, hi; };

__device__ __forceinline__ B128 b_load(const uint4* arr, int row) {
    uint4 q = arr[row];
    B128 r;
    r.lo = (u64)q.x | ((u64)q.y << 32);
    r.hi = (u64)q.z | ((u64)q.w << 32);
    return r;
}
__device__ __forceinline__ void b_store(uint4* arr, int row, B128 v) {
    arr[row] = make_uint4((u32)v.lo, (u32)(v.lo >> 32), (u32)v.hi, (u32)(v.hi >> 32));
}
__device__ __forceinline__ B128 b_and(B128 a, B128 b) { return {a.lo & b.lo, a.hi & b.hi}; }
__device__ __forceinline__ B128 b_not(B128 a) { return {~a.lo, ~a.hi}; }
__device__ __forceinline__ B128 b_shl1(B128 a) { return {a.lo << 1, (a.hi << 1) | (a.lo >> 63)}; }
__device__ __forceinline__ B128 b_shr1(B128 a) { return {(a.lo >> 1) | (a.hi << 63), a.hi >> 1}; }
__device__ __forceinline__ bool b_any(B128 a) { return (a.lo | a.hi) != 0ULL; }
__device__ __forceinline__ int  b_pop(B128 a) { return __popcll(a.lo) + __popcll(a.hi); }
__device__ __forceinline__ B128 b_starts(B128 o) { B128 s = b_shl1(o); return {o.lo & ~s.lo, o.hi & ~s.hi}; }
// popcount of start bits strictly below global bit position b (b in [0,128])
__device__ __forceinline__ int b_popbelow(B128 s, int b) {
    if (b == 0) return 0;
    if (b <= 64) {
        u64 m = (b == 64) ? ~0ULL : ((1ULL << b) - 1ULL);
        return __popcll(s.lo & m);
    }
    int bb = b - 64;
    u64 m = (bb >= 64) ? ~0ULL : ((1ULL << bb) - 1ULL);
    return __popcll(s.lo) + __popcll(s.hi & m);
}
__device__ __forceinline__ int cto64(u64 x) {
    u64 inv = ~x;
    return inv ? (__ffsll((long long)inv) - 1) : 64;
}
__device__ __forceinline__ int b_runlen(B128 o, int b) {
    B128 sh;
    if (b == 0) sh = o;
    else if (b < 64) { sh.lo = (o.lo >> b) | (o.hi << (64 - b)); sh.hi = o.hi >> b; }
    else { sh.lo = o.hi >> (b - 64); sh.hi = 0; }
    int c = cto64(sh.lo);
    if (c == 64) c += cto64(sh.hi);
    return c;
}

// ---------------- global union-find (sentinel roots: P[x] >= RCAP) --------
__device__ __forceinline__ int uf_find(int* P, int x) {
    while (true) {
        int p = P[x];
        if (p >= RCAP) return x;
        int gp = P[p];
        if (gp >= RCAP) return p;
        P[x] = gp;
        x = gp;
    }
}
__device__ __forceinline__ void uf_union(int* P, int a, int b) {
    while (true) {
        a = uf_find(P, a);
        b = uf_find(P, b);
        if (a == b) return;
        if (a > b) { int t = a; a = b; b = t; }
        int old = atomicMin(&P[b], a);
        if (old >= RCAP || old == b) return;
        b = old;
    }
}

// ---------------- plane-local union-find (shared; roots: >= PRUN) ---------
__device__ __forceinline__ int l_find(int* P, int x) {
    while (true) {
        int p = P[x];
        if (p >= PRUN) return x;
        int gp = P[p];
        if (gp >= PRUN) return p;
        P[x] = gp;
        x = gp;
    }
}
__device__ __forceinline__ void l_union(int* P, int a, int b) {
    while (true) {
        a = l_find(P, a);
        b = l_find(P, b);
        if (a == b) return;
        if (a > b) { int t = a; a = b; b = t; }
        int old = atomicMin(&P[b], a);
        if (old >= PRUN || old == b) return;
        b = old;
    }
}

// occupancy for problem p, row r
__device__ __forceinline__ B128 get_occ(int p, int row) {
    if (p < 12) return b_load(g_mbits[p], row);
    if (p < 24) return b_load(g_ebits[p - 12], row);
    return b_not(b_load(g_mbits[p - 24], row));
}

// ---------------- kernels ----------------

// Warp per (batch,row): softmax+threshold -> 6 bitmap rows.  grid 2048 x 256
__global__ void k_masks(const float* __restrict__ pred, const int* __restrict__ target) {
    int gw = blockIdx.x * 8 + (threadIdx.x >> 5);
    int lane = threadIdx.x & 31;
    int b = gw >> 13;
    int row = gw & (NROWS - 1);
    int v = row * WX + lane * 4;

    const float* pp = pred + (size_t)b * 4 * NVOX + v;
    float4 a0 = *(const float4*)(pp);
    float4 a1 = *(const float4*)(pp + NVOX);
    float4 a2 = *(const float4*)(pp + 2 * NVOX);
    float4 a3 = *(const float4*)(pp + 3 * NVOX);
    int4 t = *(const int4*)(target + (size_t)b * NVOX + v);

    float x0s[4] = {a0.x, a0.y, a0.z, a0.w};
    float x1s[4] = {a1.x, a1.y, a1.z, a1.w};
    float x2s[4] = {a2.x, a2.y, a2.z, a2.w};
    float x3s[4] = {a3.x, a3.y, a3.z, a3.w};
    u32 nib[6] = {0, 0, 0, 0, 0, 0};
    #pragma unroll
    for (int i = 0; i < 4; i++) {
        float m = fmaxf(fmaxf(x0s[i], x1s[i]), fmaxf(x2s[i], x3s[i]));
        float e0 = expf(x0s[i] - m), e1 = expf(x1s[i] - m);
        float e2 = expf(x2s[i] - m), e3 = expf(x3s[i] - m);
        float h = 0.5f * (e0 + e1 + e2 + e3);
        nib[0] |= (e1 > h) << i;
        nib[1] |= (e2 > h) << i;
        nib[2] |= (e3 > h) << i;
    }
    int ts[4] = {t.x, t.y, t.z, t.w};
    #pragma unroll
    for (int i = 0; i < 4; i++) {
        nib[3] |= (ts[i] == 1) << i;
        nib[4] |= (ts[i] == 2) << i;
        nib[5] |= (ts[i] == 3) << i;
    }
    int sh = (lane & 7) * 4;
    int widx = lane >> 3;
    #pragma unroll
    for (int k = 0; k < 6; k++) {
        u32 seg = nib[k] << sh;
        seg |= __shfl_xor_sync(0xFFFFFFFFu, seg, 1);
        seg |= __shfl_xor_sync(0xFFFFFFFFu, seg, 2);
        seg |= __shfl_xor_sync(0xFFFFFFFFu, seg, 4);
        if ((lane & 7) == 0) {
            int mi = (k < 3) ? (b * 3 + k) : (6 + b * 3 + (k - 3));
            ((u32*)&g_mbits[mi][row])[widx] = seg;
        }
    }
}

// Erosion on bitmaps.  grid (32,12) x 256 ; thread per row
__global__ void k_erode() {
    int row = blockIdx.x * 256 + threadIdx.x;
    int mi = blockIdx.y;
    int y = row & (HY - 1);
    int z = row >> 7;
    B128 e;
    if (y == 0 || y == HY - 1 || z == 0 || z == DZ - 1) {
        e.lo = 0; e.hi = 0;
    } else {
        B128 m  = b_load(g_mbits[mi], row);
        B128 up = b_load(g_mbits[mi], row - 1);
        B128 dn = b_load(g_mbits[mi], row + 1);
        B128 fr = b_load(g_mbits[mi], row - HY);
        B128 bk = b_load(g_mbits[mi], row + HY);
        B128 ml = b_shl1(m), mr = b_shr1(m);
        e.lo = m.lo & ml.lo & mr.lo & up.lo & dn.lo & fr.lo & bk.lo;
        e.hi = m.hi & ml.hi & mr.hi & up.hi & dn.hi & fr.hi & bk.hi;
    }
    b_store(g_ebits[mi], row, e);
}

// Plane-local CC: all y-pair merges for one z-plane in shared-memory UF,
// then write flattened parents to g_P (and zero g_R window, g_cnt).
// grid (DZ=64, 36) x 256
__global__ void __launch_bounds__(256) k_plane() {
    __shared__ u64 sLo[128], sHi[128];    // occupancy per row
    __shared__ u64 tLo[128], tHi[128];    // run starts per row
    __shared__ int sP[PRUN];              // plane-local UF (32 KB)

    int tid = threadIdx.x;
    int z = blockIdx.x;
    int p = blockIdx.y;

    if (tid < 128) {
        B128 o = get_occ(p, z * HY + tid);
        sLo[tid] = o.lo; sHi[tid] = o.hi;
        B128 st = b_starts(o);
        tLo[tid] = st.lo; tHi[tid] = st.hi;
    }
    {
        int4 sv = make_int4(LSEN, LSEN, LSEN, LSEN);
        #pragma unroll
        for (int j = 0; j < 8; j++)
            ((int4*)sP)[tid + j * 256] = sv;
    }
    __syncthreads();

    // y-pair merges: tasks t = (y-1)*2 + half, y in [1,128), half in {0,1}
    if (tid < 254) {
        int y = (tid >> 1) + 1, half = tid & 1;
        u64 oA = half ? sHi[y] : sLo[y];
        u64 oB = half ? sHi[y - 1] : sLo[y - 1];
        u64 pr = oA & oB;
        if (pr) {
            u64 carry = half ? ((sLo[y] & sLo[y - 1]) >> 63) : 0ULL;
            u64 w = pr & ~((pr << 1) | carry);
            if (w) {
                B128 sA = {tLo[y], tHi[y]};
                B128 sB = {tLo[y - 1], tHi[y - 1]};
                int boff = half * 64;
                while (w) {
                    int b = __ffsll((long long)w) - 1; w &= w - 1;
                    int gb = b + boff;
                    l_union(sP, y * 64 + (b_popbelow(sA, gb + 1) - 1),
                                (y - 1) * 64 + (b_popbelow(sB, gb + 1) - 1));
                }
            }
        }
    }
    __syncthreads();

    // flatten + write global parents (coalesced int4)
    {
        int gbase = z * PRUN;
        int* Pg = g_P + (size_t)p * RCAP + gbase;
        #pragma unroll
        for (int j = 0; j < 8; j++) {
            int idx = tid + j * 256;     // int4 index
            int i = idx * 4;
            int4 o4;
            int v;
            v = sP[i];     o4.x = (v >= PRUN) ? SEN : (gbase + l_find(sP, i));
            v = sP[i + 1]; o4.y = (v >= PRUN) ? SEN : (gbase + l_find(sP, i + 1));
            v = sP[i + 2]; o4.z = (v >= PRUN) ? SEN : (gbase + l_find(sP, i + 2));
            v = sP[i + 3]; o4.w = (v >= PRUN) ? SEN : (gbase + l_find(sP, i + 3));
            ((int4*)Pg)[idx] = o4;
        }
        if (p >= 24) {
            uint4* Rg = (uint4*)(g_R + (size_t)(p - 24) * RCAP + gbase);
            uint4 zv = make_uint4(0, 0, 0, 0);
            Rg[tid] = zv;
            Rg[tid + 256] = zv;
        }
        if (p == 0 && z == 0 && tid < NPROB) g_cnt[tid] = 0;
    }
}

// Cross-plane (z-pair) merges on pre-coarsened operands.
// 2 threads per pair; 63*128=8064 pairs/problem.  grid (63,36) x 256
__global__ void k_zmerge() {
    int t = blockIdx.x * 256 + threadIdx.x;   // [0, 16128)
    int pairid = t >> 1, half = t & 1;
    int p = blockIdx.y;
    int z = pairid >> 7, y = pairid & 127;    // z in [0,63) -> plane z+1 vs z
    int rowA = (z + 1) * HY + y;
    int rowB = rowA - HY;
    B128 oA = get_occ(p, rowA);
    B128 oB = get_occ(p, rowB);
    B128 pr = b_and(oA, oB);
    B128 ps = b_starts(pr);
    u64 w = half ? ps.hi : ps.lo;
    if (!w) return;
    B128 sA = b_starts(oA);
    B128 sB = b_starts(oB);
    int baseA = rowA * 64, baseB = rowB * 64;
    int boff = half * 64;
    int* P = g_P + (size_t)p * RCAP;
    while (w) {
        int b = __ffsll((long long)w) - 1; w &= w - 1;
        int gb = b + boff;
        uf_union(P, baseA + b_popbelow(sA, gb + 1) - 1,
                    baseB + b_popbelow(sB, gb + 1) - 1);
    }
}

// Mark bg components reaching the volume border. 4 threads/row.  grid (128,12) x 256
__global__ void k_bordermark() {
    int t = blockIdx.x * 256 + threadIdx.x;
    int row = t >> 2, w = t & 3;
    int pb = blockIdx.y;
    int p = 24 + pb;
    int y = row & (HY - 1);
    int z = row >> 7;
    B128 occ = get_occ(p, row);
    if (!b_any(occ)) return;
    int base = row * 64;
    int* P = g_P + (size_t)p * RCAP;
    u8* R = g_R + (size_t)pb * RCAP;
    B128 st = b_starts(occ);
    bool borderrow = (z == 0) || (z == DZ - 1) || (y == 0) || (y == HY - 1);
    if (borderrow) {
        u32 stw = (w < 2) ? (u32)(st.lo >> (w * 32)) : (u32)(st.hi >> ((w - 2) * 32));
        if (!stw) return;
        int k = b_popbelow(st, w * 32);
        while (stw) {
            stw &= stw - 1;
            R[uf_find(P, base + k)] = 1;
            k++;
        }
    } else {
        if (w == 0) {
            if (occ.lo & 1ULL) R[uf_find(P, base)] = 1;
        } else if (w == 3) {
            if (occ.hi >> 63) R[uf_find(P, base + b_pop(st) - 1)] = 1;
        }
    }
}

// Count roots (p<24) / cavity voxels (p>=24). 4 threads/row.  grid (128,36) x 256
__global__ void k_count() {
    int t = blockIdx.x * 256 + threadIdx.x;
    int row = t >> 2, w = t & 3;
    int p = blockIdx.y;
    B128 occ = get_occ(p, row);
    int c = 0;
    if (b_any(occ)) {
        B128 st = b_starts(occ);
        u32 stw = (w < 2) ? (u32)(st.lo >> (w * 32)) : (u32)(st.hi >> ((w - 2) * 32));
        if (stw) {
            int base = row * 64;
            int* P = g_P + (size_t)p * RCAP;
            int k = b_popbelow(st, w * 32);
            if (p < 24) {
                while (stw) {
                    stw &= stw - 1;
                    c += (P[base + k] >= RCAP);
                    k++;
                }
            } else {
                const u8* R = g_R + (size_t)(p - 24) * RCAP;
                int boff = w * 32;
                while (stw) {
                    int b = __ffs(stw) - 1; stw &= stw - 1;
                    if (!R[uf_find(P, base + k)]) c += b_runlen(occ, b + boff);
                    k++;
                }
            }
        }
    }
    #pragma unroll
    for (int off = 16; off > 0; off >>= 1)
        c += __shfl_down_sync(0xFFFFFFFFu, c, off);
    __shared__ int ssum;
    if (threadIdx.x == 0) ssum = 0;
    __syncthreads();
    if ((threadIdx.x & 31) == 0 && c) atomicAdd(&ssum, c);
    __syncthreads();
    if (threadIdx.x == 0 && ssum) atomicAdd(&g_cnt[p], ssum);
}

__device__ __forceinline__ int iabs_(int a) { return a < 0 ? -a : a; }
__device__ __forceinline__ int imax0_(int a) { return a > 0 ? a : 0; }

__global__ void k_final(float* __restrict__ out) {
    float tot = 0.0f;
    #pragma unroll
    for (int i = 0; i < 6; i++) {
        int pb0 = g_cnt[i],      tb0 = g_cnt[i + 6];
        int pbe = g_cnt[12 + i], tbe = g_cnt[12 + i + 6];
        int pcv = g_cnt[24 + i], tcv = g_cnt[24 + i + 6];
        int pb1 = imax0_(pb0 - pbe), tb1 = imax0_(tb0 - tbe);
        int pb2 = pcv / 100,         tb2 = tcv / 100;
        tot += (float)(iabs_(pb0 - tb0) + iabs_(pb1 - tb1) + iabs_(pb2 - tb2));
    }
    out[0] = 0.1f * tot / 6.0f;
}

// ---------------- launch ----------------
extern "C" void kernel_launch(void* const* d_in, const int* in_sizes, int n_in,
                              void* d_out, int out_size) {
    const float* pred   = (const float*)d_in[0];
    const int*   target = (const int*)d_in[1];
    float*       out    = (float*)d_out;

    k_masks<<<2048, 256>>>(pred, target);
    k_erode<<<dim3(32, 12), 256>>>();
    k_plane<<<dim3(DZ, NPROB), 256>>>();
    k_zmerge<<<dim3(63, NPROB), 256>>>();
    k_bordermark<<<dim3(128, 12), 256>>>();
    k_count<<<dim3(128, NPROB), 256>>>();
    k_final<<<1, 1>>>(out);
}